// round 11
// baseline (speedup 1.0000x reference)
#include <cuda_runtime.h>

#define Bq   256
#define Tq   1024
#define NUMq 126
#define LBLq 128
#define NWORK 296   // 2 persistent CTAs per SM (148 SMs)

__device__ int d_perm[Bq];
__device__ int d_next;

// Rank sequences by length (desc) and reset the work counter.
__global__ void rank_kernel(const int* __restrict__ lens) {
    __shared__ int sl[Bq];
    int i = threadIdx.x;
    int li = lens[i];
    sl[i] = li;
    if (i == 0) d_next = 0;
    __syncthreads();
    int r = 0;
    #pragma unroll 8
    for (int k = 0; k < Bq; ++k) {
        int lk = sl[k];
        r += (lk > li) || (lk == li && k < i);
    }
    d_perm[r] = i;
}

__device__ __forceinline__ void fma2(unsigned long long& d,
                                     unsigned long long a, unsigned long long b) {
    asm("fma.rn.f32x2 %0, %1, %2, %0;" : "+l"(d) : "l"(a), "l"(b));
}
__device__ __forceinline__ unsigned long long add2(unsigned long long a,
                                                   unsigned long long b) {
    unsigned long long d;
    asm("add.rn.f32x2 %0, %1, %2;" : "=l"(d) : "l"(a), "l"(b));
    return d;
}
__device__ __forceinline__ unsigned long long pack2(float lo, float hi) {
    unsigned long long d;
    asm("mov.b64 %0, {%1, %2};" : "=l"(d) : "f"(lo), "f"(hi));
    return d;
}
__device__ __forceinline__ void unpack2(unsigned long long d, float& lo, float& hi) {
    asm("mov.b64 {%0, %1}, %2;" : "=f"(lo), "=f"(hi) : "l"(d));
}

__global__ __launch_bounds__(128, 2)
void crf_kernel(const float* __restrict__ logits,
                const int*   __restrict__ labels,
                const int*   __restrict__ lens,
                const float* __restrict__ trans,
                float*       __restrict__ out) {
    const int tid = threadIdx.x;
    const int w   = tid >> 5;
    const int l   = tid & 31;
    const int h   = l >> 4;               // k-half (64 cols each)
    const int g   = l & 15;               // row-group within warp
    const int rowbase = w * 32 + g * 2;   // this thread's 2 output rows

    __shared__ __align__(128) float abuf[2][LBLq];
    __shared__ float red[4];
    __shared__ int   s_slot;

    // ---- expT tile: 2 rows x 64 cols (half h) — loaded ONCE per worker ----
    unsigned long long R2[2][32];
    #pragma unroll
    for (int r = 0; r < 2; ++r) {
        const float4* trow = (const float4*)(trans + (rowbase + r) * LBLq + h * 64);
        #pragma unroll
        for (int s = 0; s < 16; ++s) {
            float4 v = trow[s];
            R2[r][2 * s]     = pack2(__expf(v.x), __expf(v.y));
            R2[r][2 * s + 1] = pack2(__expf(v.z), __expf(v.w));
        }
    }
    float vmask[2];
    vmask[0] = (rowbase + 0 < NUMq) ? 1.f : 0.f;
    vmask[1] = (rowbase + 1 < NUMq) ? 1.f : 0.f;
    const int rr0 = (rowbase + 0 < NUMq) ? (rowbase + 0) : (NUMq - 1);
    const int rr1 = (rowbase + 1 < NUMq) ? (rowbase + 1) : (NUMq - 1);

    // ---- persistent work loop: pull next-longest remaining sequence ----
    for (;;) {
        if (tid == 0) s_slot = atomicAdd(&d_next, 1);
        __syncthreads();
        const int slot = s_slot;
        __syncthreads();          // everyone has read s_slot before reuse
        if (slot >= Bq) break;

        const int b   = d_perm[slot];
        const int len = lens[b];
        const int lb  = b * Tq;
        const float* lgb = logits + (size_t)lb * NUMq;

        // ---- gold path score (cooperative over t) ----
        float gacc = 0.f;
        for (int t = tid; t < len; t += 128) {
            int lab = labels[lb + t];
            gacc += lgb[t * NUMq + lab];
            int prev = (t == 0) ? (LBLq - 2) : labels[lb + t - 1];
            gacc += trans[lab * LBLq + prev];
        }
        if (tid == 0) gacc += trans[(LBLq - 1) * LBLq + labels[lb + len - 1]];
        #pragma unroll
        for (int d = 16; d >= 1; d >>= 1)
            gacc += __shfl_xor_sync(0xffffffffu, gacc, d);
        if (l == 0) red[w] = gacc;
        __syncthreads();
        float gold = 0.f;
        if (tid == 0) gold = (red[0] + red[1]) + (red[2] + red[3]);

        // ---- init alpha0 = onehot(start=126) ----
        abuf[0][tid] = (tid == (LBLq - 2)) ? 1.0f : 0.0f;

        // ---- logit queues + precomputed exp weights for current group ----
        float cur[4][2], nxt[4][2], we[4][2];
        #pragma unroll
        for (int q = 0; q < 4; ++q) {
            int tt = (q < len) ? q : (len - 1);
            cur[q][0] = lgb[tt * NUMq + rr0];
            cur[q][1] = lgb[tt * NUMq + rr1];
            int t2 = (4 + q < len) ? (4 + q) : (len - 1);
            nxt[q][0] = lgb[t2 * NUMq + rr0];
            nxt[q][1] = lgb[t2 * NUMq + rr1];
        }
        #pragma unroll
        for (int q = 0; q < 4; ++q) {
            we[q][0] = __expf(cur[q][0]) * vmask[0];
            we[q][1] = __expf(cur[q][1]) * vmask[1];
        }

        float logc = 0.f;
        float inv  = 1.0f;
        __syncthreads();

#define STEP(PH, T)                                                             \
    {                                                                           \
        const int rb = (PH) & 1, wb = 1 - rb;                                   \
        if ((PH) == 0 && (T) != 0) {                                            \
            _Pragma("unroll")                                                   \
            for (int q = 0; q < 4; ++q) {                                       \
                cur[q][0] = nxt[q][0];                                          \
                cur[q][1] = nxt[q][1];                                          \
                int tt = ((T) + 4 + q < len) ? ((T) + 4 + q) : (len - 1);       \
                nxt[q][0] = lgb[tt * NUMq + rr0];                               \
                nxt[q][1] = lgb[tt * NUMq + rr1];                               \
            }                                                                   \
            _Pragma("unroll")                                                   \
            for (int q = 0; q < 4; ++q) {                                       \
                we[q][0] = __expf(cur[q][0]) * vmask[0];                        \
                we[q][1] = __expf(cur[q][1]) * vmask[1];                        \
            }                                                                   \
        }                                                                       \
        const ulonglong2* aa = (const ulonglong2*)(abuf[rb] + h * 64);          \
        unsigned long long a00 = 0ull, a01 = 0ull, a02 = 0ull, a03 = 0ull;      \
        unsigned long long a10 = 0ull, a11 = 0ull, a12 = 0ull, a13 = 0ull;      \
        unsigned long long s0 = 0ull, s1 = 0ull;                                \
        _Pragma("unroll")                                                       \
        for (int s = 0; s < 16; ++s) {                                          \
            ulonglong2 A = aa[s];                                               \
            if ((PH) == 0) { s0 = add2(s0, A.x); s1 = add2(s1, A.y); }          \
            if (s & 1) {                                                        \
                fma2(a02, R2[0][2 * s], A.x); fma2(a03, R2[0][2 * s + 1], A.y); \
                fma2(a12, R2[1][2 * s], A.x); fma2(a13, R2[1][2 * s + 1], A.y); \
            } else {                                                            \
                fma2(a00, R2[0][2 * s], A.x); fma2(a01, R2[0][2 * s + 1], A.y); \
                fma2(a10, R2[1][2 * s], A.x); fma2(a11, R2[1][2 * s + 1], A.y); \
            }                                                                   \
        }                                                                       \
        if ((PH) == 0) {                                                        \
            float tlo, thi;                                                     \
            unpack2(add2(s0, s1), tlo, thi);                                    \
            float ts = tlo + thi;                                               \
            ts += __shfl_xor_sync(0xffffffffu, ts, 16);                         \
            inv   = __fdividef(1.0f, ts);                                       \
            logc += __logf(ts);                                                 \
        }                                                                       \
        float lo, hi, ps0, ps1;                                                 \
        unpack2(add2(add2(a00, a01), add2(a02, a03)), lo, hi); ps0 = lo + hi;   \
        ps0 += __shfl_xor_sync(0xffffffffu, ps0, 16);                           \
        unpack2(add2(add2(a10, a11), add2(a12, a13)), lo, hi); ps1 = lo + hi;   \
        ps1 += __shfl_xor_sync(0xffffffffu, ps1, 16);                           \
        float w0 = we[(PH)][0], w1 = we[(PH)][1];                               \
        if ((PH) == 1) { w0 *= inv; w1 *= inv; }                                \
        if (h == 0)                                                             \
            *(float2*)&abuf[wb][rowbase] = make_float2(w0 * ps0, w1 * ps1);     \
        __syncthreads();                                                        \
    }

        int t0 = 0;
        for (; t0 + 4 <= len; t0 += 4) {
            STEP(0, t0)
            STEP(1, t0 + 1)
            STEP(2, t0 + 2)
            STEP(3, t0 + 3)
        }
        const int rem = len - t0;
        if (rem > 0) STEP(0, t0)
        if (rem > 1) STEP(1, t0 + 1)
        if (rem > 2) STEP(2, t0 + 2)
#undef STEP

        // ---- finish: alpha *= exp(trans[end]); fold pending inv ----
        const int rbf = len & 1;
        float fv = abuf[rbf][tid] * __expf(trans[(LBLq - 1) * LBLq + tid]);
        if ((len & 3) == 1) fv *= inv;
        #pragma unroll
        for (int d = 16; d >= 1; d >>= 1)
            fv += __shfl_xor_sync(0xffffffffu, fv, d);
        if (l == 0) red[w] = fv;
        __syncthreads();
        if (tid == 0) {
            float fs = (red[0] + red[1]) + (red[2] + red[3]);
            out[b] = gold - (logc + __logf(fs));
        }
        __syncthreads();   // protect red[] / abuf before next sequence
    }
}

extern "C" void kernel_launch(void* const* d_in, const int* in_sizes, int n_in,
                              void* d_out, int out_size) {
    const float* logits = (const float*)d_in[0];
    const int*   labels = (const int*)d_in[1];
    const int*   lens   = (const int*)d_in[2];
    const float* trans  = (const float*)d_in[3];
    float*       out    = (float*)d_out;

    rank_kernel<<<1, Bq>>>(lens);
    crf_kernel<<<NWORK, 128>>>(logits, labels, lens, trans, out);
}

// round 13
// speedup vs baseline: 1.5226x; 1.5226x over previous
#include <cuda_runtime.h>

#define Bq   256
#define Tq   1024
#define NUMq 126
#define LBLq 128

__device__ int   d_perm[Bq];
__device__ float d_vecA[Bq][LBLq];   // alpha_m  (forward half result)
__device__ float d_vecB[Bq][LBLq];   // z_m      (backward half result)
__device__ float d_lcA[Bq];
__device__ float d_lcB[Bq];

// Rank sequences by length (desc): CTA bid order = longest halves first (LPT-ish).
__global__ void rank_kernel(const int* __restrict__ lens) {
    __shared__ int sl[Bq];
    int i = threadIdx.x;
    int li = lens[i];
    sl[i] = li;
    __syncthreads();
    int r = 0;
    #pragma unroll 8
    for (int k = 0; k < Bq; ++k) {
        int lk = sl[k];
        r += (lk > li) || (lk == li && k < i);
    }
    d_perm[r] = i;
}

__device__ __forceinline__ void fma2(unsigned long long& d,
                                     unsigned long long a, unsigned long long b) {
    asm("fma.rn.f32x2 %0, %1, %2, %0;" : "+l"(d) : "l"(a), "l"(b));
}
__device__ __forceinline__ unsigned long long add2(unsigned long long a,
                                                   unsigned long long b) {
    unsigned long long d;
    asm("add.rn.f32x2 %0, %1, %2;" : "=l"(d) : "l"(a), "l"(b));
    return d;
}
__device__ __forceinline__ unsigned long long pack2(float lo, float hi) {
    unsigned long long d;
    asm("mov.b64 %0, {%1, %2};" : "=l"(d) : "f"(lo), "f"(hi));
    return d;
}
__device__ __forceinline__ void unpack2(unsigned long long d, float& lo, float& hi) {
    asm("mov.b64 {%0, %1}, %2;" : "=f"(lo), "=f"(hi) : "l"(d));
}

// One CTA = one half-scan. bid>>1 = rank slot, bid&1 = direction (0 fwd, 1 bwd).
__global__ __launch_bounds__(128, 2)
void crf_scan(const float* __restrict__ logits,
              const int*   __restrict__ lens,
              const float* __restrict__ trans) {
    const int slot = blockIdx.x >> 1;
    const int dir  = blockIdx.x & 1;
    const int b    = d_perm[slot];
    const int len  = lens[b];
    const int m    = (len - 1) >> 1;             // fwd steps
    const int nsteps = dir ? (len - 1 - m) : m;  // this CTA's weighted steps

    const int tid = threadIdx.x;
    const int l   = tid & 31;
    const int h   = l >> 4;               // k-half (64 cols each)
    const int g   = l & 15;               // row-group within warp
    const int rowbase = (tid >> 5) * 32 + g * 2;

    __shared__ __align__(128) float abuf[2][LBLq];

    // ---- tile: 2 rows x 64 cols of M (fwd) or M^T (bwd) ----
    unsigned long long R2[2][32];
    if (dir == 0) {
        #pragma unroll
        for (int r = 0; r < 2; ++r) {
            const float4* trow = (const float4*)(trans + (rowbase + r) * LBLq + h * 64);
            #pragma unroll
            for (int s = 0; s < 16; ++s) {
                float4 v = trow[s];
                R2[r][2 * s]     = pack2(__expf(v.x), __expf(v.y));
                R2[r][2 * s + 1] = pack2(__expf(v.z), __expf(v.w));
            }
        }
    } else {
        #pragma unroll
        for (int r = 0; r < 2; ++r) {
            const int k = rowbase + r;           // row of M^T = column of M
            #pragma unroll
            for (int s = 0; s < 16; ++s) {
                int j = h * 64 + 4 * s;
                R2[r][2 * s]     = pack2(__expf(trans[(j + 0) * LBLq + k]),
                                         __expf(trans[(j + 1) * LBLq + k]));
                R2[r][2 * s + 1] = pack2(__expf(trans[(j + 2) * LBLq + k]),
                                         __expf(trans[(j + 3) * LBLq + k]));
            }
        }
    }
    float vmask[2];
    vmask[0] = (rowbase + 0 < NUMq) ? 1.f : 0.f;
    vmask[1] = (rowbase + 1 < NUMq) ? 1.f : 0.f;
    const int rr0 = (rowbase + 0 < NUMq) ? (rowbase + 0) : (NUMq - 1);
    const int rr1 = (rowbase + 1 < NUMq) ? (rowbase + 1) : (NUMq - 1);

    const float* lgb = logits + (size_t)b * Tq * NUMq;

    // ---- init ----
    if (dir == 0) {
        abuf[0][tid] = (tid == (LBLq - 2)) ? 1.0f : 0.0f;
    } else {
        // u_0[j] = exp(trans[end][j] + lg[len-1, j]), masked
        abuf[0][tid] = (tid < NUMq)
            ? __expf(trans[(LBLq - 1) * LBLq + tid] + lgb[(len - 1) * NUMq + tid])
            : 0.f;
    }

    // logit stream: idx(t) = t (fwd) or len-2-t (bwd)
    const int sbase = dir ? (len - 2) : 0;
    const int ssgn  = dir ? -1 : 1;

    float cur[4][2], nxt[4][2], we[4][2];
    if (nsteps > 0) {
        #pragma unroll
        for (int q = 0; q < 4; ++q) {
            int tt = (q < nsteps) ? q : (nsteps - 1);
            int li0 = sbase + ssgn * tt;
            cur[q][0] = lgb[li0 * NUMq + rr0];
            cur[q][1] = lgb[li0 * NUMq + rr1];
            int t2 = (4 + q < nsteps) ? (4 + q) : (nsteps - 1);
            int li1 = sbase + ssgn * t2;
            nxt[q][0] = lgb[li1 * NUMq + rr0];
            nxt[q][1] = lgb[li1 * NUMq + rr1];
        }
        #pragma unroll
        for (int q = 0; q < 4; ++q) {
            we[q][0] = __expf(cur[q][0]) * vmask[0];
            we[q][1] = __expf(cur[q][1]) * vmask[1];
        }
    }

    float logc = 0.f;
    float inv  = 1.0f;
    __syncthreads();

#define STEP(PH, T)                                                             \
    {                                                                           \
        const int rb = (PH) & 1, wb = 1 - rb;                                   \
        if ((PH) == 0 && (T) != 0) {                                            \
            _Pragma("unroll")                                                   \
            for (int q = 0; q < 4; ++q) {                                       \
                cur[q][0] = nxt[q][0];                                          \
                cur[q][1] = nxt[q][1];                                          \
                int tt = ((T) + 4 + q < nsteps) ? ((T) + 4 + q) : (nsteps - 1); \
                int li2 = sbase + ssgn * tt;                                    \
                nxt[q][0] = lgb[li2 * NUMq + rr0];                              \
                nxt[q][1] = lgb[li2 * NUMq + rr1];                              \
            }                                                                   \
            _Pragma("unroll")                                                   \
            for (int q = 0; q < 4; ++q) {                                       \
                we[q][0] = __expf(cur[q][0]) * vmask[0];                        \
                we[q][1] = __expf(cur[q][1]) * vmask[1];                        \
            }                                                                   \
        }                                                                       \
        const ulonglong2* aa = (const ulonglong2*)(abuf[rb] + h * 64);          \
        unsigned long long a00 = 0ull, a01 = 0ull, a02 = 0ull, a03 = 0ull;      \
        unsigned long long a10 = 0ull, a11 = 0ull, a12 = 0ull, a13 = 0ull;      \
        unsigned long long s0 = 0ull, s1 = 0ull;                                \
        _Pragma("unroll")                                                       \
        for (int s = 0; s < 16; ++s) {                                          \
            ulonglong2 A = aa[s];                                               \
            if ((PH) == 0) { s0 = add2(s0, A.x); s1 = add2(s1, A.y); }          \
            if (s & 1) {                                                        \
                fma2(a02, R2[0][2 * s], A.x); fma2(a03, R2[0][2 * s + 1], A.y); \
                fma2(a12, R2[1][2 * s], A.x); fma2(a13, R2[1][2 * s + 1], A.y); \
            } else {                                                            \
                fma2(a00, R2[0][2 * s], A.x); fma2(a01, R2[0][2 * s + 1], A.y); \
                fma2(a10, R2[1][2 * s], A.x); fma2(a11, R2[1][2 * s + 1], A.y); \
            }                                                                   \
        }                                                                       \
        if ((PH) == 0) {                                                        \
            float tlo, thi;                                                     \
            unpack2(add2(s0, s1), tlo, thi);                                    \
            float ts = tlo + thi;                                               \
            ts += __shfl_xor_sync(0xffffffffu, ts, 16);                         \
            inv   = __fdividef(1.0f, ts);                                       \
            logc += __logf(ts);                                                 \
        }                                                                       \
        float lo, hi, ps0, ps1;                                                 \
        unpack2(add2(add2(a00, a01), add2(a02, a03)), lo, hi); ps0 = lo + hi;   \
        ps0 += __shfl_xor_sync(0xffffffffu, ps0, 16);                           \
        unpack2(add2(add2(a10, a11), add2(a12, a13)), lo, hi); ps1 = lo + hi;   \
        ps1 += __shfl_xor_sync(0xffffffffu, ps1, 16);                           \
        float w0 = we[(PH)][0], w1 = we[(PH)][1];                               \
        if ((PH) == 1) { w0 *= inv; w1 *= inv; }                                \
        if (h == 0)                                                             \
            *(float2*)&abuf[wb][rowbase] = make_float2(w0 * ps0, w1 * ps1);     \
        __syncthreads();                                                        \
    }

    int t0 = 0;
    for (; t0 + 4 <= nsteps; t0 += 4) {
        STEP(0, t0)
        STEP(1, t0 + 1)
        STEP(2, t0 + 2)
        STEP(3, t0 + 3)
    }
    const int rem = nsteps - t0;
    if (rem > 0) STEP(0, t0)
    if (rem > 1) STEP(1, t0 + 1)
    if (rem > 2) STEP(2, t0 + 2)
#undef STEP

    const float pend = ((nsteps & 3) == 1) ? inv : 1.0f;

    if (dir == 0) {
        // write alpha_m (fold pending inv)
        d_vecA[b][tid] = abuf[nsteps & 1][tid] * pend;
        if (tid == 0) d_lcA[b] = logc;
    } else {
        // one extra UNWEIGHTED M^T matvec -> z_m, then write
        const int rb = nsteps & 1;
        const ulonglong2* aa = (const ulonglong2*)(abuf[rb] + h * 64);
        unsigned long long a00 = 0ull, a01 = 0ull, a10 = 0ull, a11 = 0ull;
        #pragma unroll
        for (int s = 0; s < 16; ++s) {
            ulonglong2 A = aa[s];
            fma2(a00, R2[0][2 * s], A.x); fma2(a01, R2[0][2 * s + 1], A.y);
            fma2(a10, R2[1][2 * s], A.x); fma2(a11, R2[1][2 * s + 1], A.y);
        }
        float lo, hi, ps0, ps1;
        unpack2(add2(a00, a01), lo, hi); ps0 = lo + hi;
        ps0 += __shfl_xor_sync(0xffffffffu, ps0, 16);
        unpack2(add2(a10, a11), lo, hi); ps1 = lo + hi;
        ps1 += __shfl_xor_sync(0xffffffffu, ps1, 16);
        if (h == 0) {
            d_vecB[b][rowbase + 0] = ps0 * pend;
            d_vecB[b][rowbase + 1] = ps1 * pend;
        }
        if (tid == 0) d_lcB[b] = logc;
    }
}

// Combine: out[b] = gold - (lcA + lcB + log(dot(vecA, vecB)))
__global__ __launch_bounds__(128, 2)
void crf_combine(const float* __restrict__ logits,
                 const int*   __restrict__ labels,
                 const int*   __restrict__ lens,
                 const float* __restrict__ trans,
                 float*       __restrict__ out) {
    const int b   = blockIdx.x;
    const int len = lens[b];
    const int tid = threadIdx.x;
    const int w   = tid >> 5;
    const int l   = tid & 31;
    __shared__ float red[4], red2[4];

    const int lb = b * Tq;
    const float* lgb = logits + (size_t)lb * NUMq;

    // gold path score
    float gacc = 0.f;
    for (int t = tid; t < len; t += 128) {
        int lab = labels[lb + t];
        gacc += lgb[t * NUMq + lab];
        int prev = (t == 0) ? (LBLq - 2) : labels[lb + t - 1];
        gacc += trans[lab * LBLq + prev];
    }
    if (tid == 0) gacc += trans[(LBLq - 1) * LBLq + labels[lb + len - 1]];

    // dot(vecA, vecB)
    float p = d_vecA[b][tid] * d_vecB[b][tid];

    #pragma unroll
    for (int d = 16; d >= 1; d >>= 1) {
        gacc += __shfl_xor_sync(0xffffffffu, gacc, d);
        p    += __shfl_xor_sync(0xffffffffu, p, d);
    }
    if (l == 0) { red[w] = gacc; red2[w] = p; }
    __syncthreads();
    if (tid == 0) {
        float gold = (red[0] + red[1]) + (red[2] + red[3]);
        float dot  = (red2[0] + red2[1]) + (red2[2] + red2[3]);
        out[b] = gold - (d_lcA[b] + d_lcB[b] + __logf(dot));
    }
}

extern "C" void kernel_launch(void* const* d_in, const int* in_sizes, int n_in,
                              void* d_out, int out_size) {
    const float* logits = (const float*)d_in[0];
    const int*   labels = (const int*)d_in[1];
    const int*   lens   = (const int*)d_in[2];
    const float* trans  = (const float*)d_in[3];
    float*       out    = (float*)d_out;

    rank_kernel<<<1, Bq>>>(lens);
    crf_scan<<<2 * Bq, 128>>>(logits, lens, trans);
    crf_combine<<<Bq, 128>>>(logits, labels, lens, trans, out);
}